// round 14
// baseline (speedup 1.0000x reference)
#include <cuda_runtime.h>
#include <math.h>

// Problem constants
#define B_  2
#define S_  2048
#define D_  1024
#define H_  16
#define L_  8
#define DH_ 64
#define M_  (B_*S_)          // 4096 rows for all projections

// Scratch (device globals; no allocations allowed)
__device__ float g_q[(size_t)B_*H_*S_*DH_];
__device__ float g_k[(size_t)B_*H_*S_*DH_];
__device__ float g_v[(size_t)B_*H_*S_*DH_];
__device__ float g_ctx[(size_t)B_*S_*D_];

// ---------------------------------------------------------------------------
// Generic tiled GEMM:  C[r,c] = sum_k A[r,k] * W[c,k] + bias[c]
//   A: [M,K] row-major, W: [N,K] row-major.
//   mode 0: write head-split   -> C0[((b*H+h)*S+s)*DH+dh],  c = h*DH+dh (N=1024)
//   mode 1: write flat         -> C0[r*N + c]
//   mode 2: N=3072 qkv split   -> part = c/1024 selects C0/C1/C2, head-split
// Tile: 128x128x8, 256 threads, 8x8 microtile per thread.
// ---------------------------------------------------------------------------
__global__ void __launch_bounds__(256)
gemm_bias_kernel(const float* __restrict__ A, const float* __restrict__ W,
                 const float* __restrict__ bias,
                 float* __restrict__ C0, float* __restrict__ C1, float* __restrict__ C2,
                 int M, int N, int K, int mode)
{
    __shared__ __align__(16) float As[8][128];
    __shared__ __align__(16) float Ws[8][128];

    const int tid  = threadIdx.x;
    const int bx   = blockIdx.x;        // N tile
    const int by   = blockIdx.y;        // M tile
    const int row0 = by * 128;
    const int col0 = bx * 128;

    const int lr = tid >> 1;            // 0..127 : tile row
    const int lk = (tid & 1) * 4;       // 0 or 4 : k sub-chunk

    const float* Aptr = A + (size_t)(row0 + lr) * K + lk;
    const float* Wptr = W + (size_t)(col0 + lr) * K + lk;

    const int tx = tid & 15;            // 0..15  : col group (8 cols)
    const int ty = tid >> 4;            // 0..15  : row group (8 rows)

    float acc[8][8];
    #pragma unroll
    for (int i = 0; i < 8; i++)
        #pragma unroll
        for (int j = 0; j < 8; j++) acc[i][j] = 0.f;

    float4 av = *(const float4*)(Aptr);
    float4 wv = *(const float4*)(Wptr);

    for (int kt = 0; kt < K; kt += 8) {
        As[lk+0][lr] = av.x; As[lk+1][lr] = av.y; As[lk+2][lr] = av.z; As[lk+3][lr] = av.w;
        Ws[lk+0][lr] = wv.x; Ws[lk+1][lr] = wv.y; Ws[lk+2][lr] = wv.z; Ws[lk+3][lr] = wv.w;
        __syncthreads();

        if (kt + 8 < K) {               // prefetch next k-slab
            av = *(const float4*)(Aptr + kt + 8);
            wv = *(const float4*)(Wptr + kt + 8);
        }

        #pragma unroll
        for (int kk = 0; kk < 8; kk++) {
            float a[8], b[8];
            *(float4*)&a[0] = *(const float4*)&As[kk][ty*8];
            *(float4*)&a[4] = *(const float4*)&As[kk][ty*8+4];
            *(float4*)&b[0] = *(const float4*)&Ws[kk][tx*8];
            *(float4*)&b[4] = *(const float4*)&Ws[kk][tx*8+4];
            #pragma unroll
            for (int i = 0; i < 8; i++)
                #pragma unroll
                for (int j = 0; j < 8; j++)
                    acc[i][j] += a[i] * b[j];
        }
        __syncthreads();
    }

    // Epilogue
    const int cbase = col0 + tx * 8;    // 8 contiguous output cols
    float bia[8];
    *(float4*)&bia[0] = *(const float4*)(bias + cbase);
    *(float4*)&bia[4] = *(const float4*)(bias + cbase + 4);

    #pragma unroll
    for (int i = 0; i < 8; i++) {
        const int r  = row0 + ty * 8 + i;
        float vals[8];
        #pragma unroll
        for (int j = 0; j < 8; j++) vals[j] = acc[i][j] + bia[j];

        if (mode == 1) {
            float* p = C0 + (size_t)r * N + cbase;
            *(float4*)p       = *(float4*)&vals[0];
            *(float4*)(p + 4) = *(float4*)&vals[4];
        } else {
            const int b_ = r >> 11;              // r / S_
            const int s_ = r & (S_ - 1);
            int d0 = cbase;
            float* Cp = C0;
            if (mode == 2) {
                const int part = cbase >> 10;    // 0:q 1:k 2:v (tile never straddles)
                d0 = cbase & 1023;
                Cp = (part == 0) ? C0 : ((part == 1) ? C1 : C2);
            }
            const int h   = d0 >> 6;
            const int dh0 = d0 & 63;             // 8-block stays inside one head
            float* p = Cp + (((size_t)(b_ * H_ + h) * S_ + s_) * DH_ + dh0);
            *(float4*)p       = *(float4*)&vals[0];
            *(float4*)(p + 4) = *(float4*)&vals[4];
        }
    }
}

// ---------------------------------------------------------------------------
// Flash attention with joint softmax over [causal tokens + L depth-memory slots].
// Grid: (S/64, B*H). 256 threads. Br=Bc=64, DH=64.
// Each thread owns a 4x4 microtile: rows ty*4+i, cols tx*4+j.
// Row-wise softmax stats reduced over the 16 tx-lanes via shfl (16-lane groups).
// ctx written directly in [B, S, H*DH] layout for the output projection.
// ---------------------------------------------------------------------------
__global__ void __launch_bounds__(256)
attn_kernel(const float* __restrict__ q, const float* __restrict__ k,
            const float* __restrict__ v, const float* __restrict__ pk,
            const float* __restrict__ pv, float* __restrict__ ctx)
{
    extern __shared__ float sm[];
    const int LDA = 65;                 // pad to dodge bank conflicts
    float* Qs = sm;
    float* Ks = Qs + 64 * LDA;
    float* Vs = Ks + 64 * LDA;
    float* Ps = Vs + 64 * LDA;

    const int qt  = blockIdx.x;
    const int bh  = blockIdx.y;
    const int b   = bh >> 4;
    const int h   = bh & 15;
    const int tid = threadIdx.x;
    const int tx  = tid & 15;
    const int ty  = tid >> 4;

    const float* qb = q + ((size_t)bh * S_ + qt * 64) * DH_;
    const float* kb = k + (size_t)bh * S_ * DH_;
    const float* vb = v + (size_t)bh * S_ * DH_;

    // Load Q tile (64x64): each thread 4 float4
    {
        const int r  = tid >> 2;
        const int c0 = (tid & 3) * 16;
        #pragma unroll
        for (int u = 0; u < 4; u++) {
            float4 t = *(const float4*)(qb + r * DH_ + c0 + u * 4);
            Qs[r*LDA + c0 + u*4 + 0] = t.x;
            Qs[r*LDA + c0 + u*4 + 1] = t.y;
            Qs[r*LDA + c0 + u*4 + 2] = t.z;
            Qs[r*LDA + c0 + u*4 + 3] = t.w;
        }
    }

    float acc[4][4];
    float mrow[4], lrow[4];
    #pragma unroll
    for (int i = 0; i < 4; i++) {
        mrow[i] = -INFINITY; lrow[i] = 0.f;
        #pragma unroll
        for (int j = 0; j < 4; j++) acc[i][j] = 0.f;
    }
    __syncthreads();

    const float scale = 0.125f;         // 1/sqrt(64)

    for (int kt = 0; kt <= qt; kt++) {
        // Load K/V tiles
        {
            const int r  = tid >> 2;
            const int c0 = (tid & 3) * 16;
            const float* kp = kb + ((size_t)kt * 64 + r) * DH_ + c0;
            const float* vp = vb + ((size_t)kt * 64 + r) * DH_ + c0;
            #pragma unroll
            for (int u = 0; u < 4; u++) {
                float4 t = *(const float4*)(kp + u * 4);
                Ks[r*LDA + c0 + u*4 + 0] = t.x;
                Ks[r*LDA + c0 + u*4 + 1] = t.y;
                Ks[r*LDA + c0 + u*4 + 2] = t.z;
                Ks[r*LDA + c0 + u*4 + 3] = t.w;
                float4 t2 = *(const float4*)(vp + u * 4);
                Vs[r*LDA + c0 + u*4 + 0] = t2.x;
                Vs[r*LDA + c0 + u*4 + 1] = t2.y;
                Vs[r*LDA + c0 + u*4 + 2] = t2.z;
                Vs[r*LDA + c0 + u*4 + 3] = t2.w;
            }
        }
        __syncthreads();

        // S = Q K^T (4x4 per thread)
        float sacc[4][4];
        #pragma unroll
        for (int i = 0; i < 4; i++)
            #pragma unroll
            for (int j = 0; j < 4; j++) sacc[i][j] = 0.f;

        #pragma unroll 8
        for (int d = 0; d < 64; d++) {
            float a0 = Qs[(ty*4+0)*LDA + d];
            float a1 = Qs[(ty*4+1)*LDA + d];
            float a2 = Qs[(ty*4+2)*LDA + d];
            float a3 = Qs[(ty*4+3)*LDA + d];
            float b0 = Ks[(tx*4+0)*LDA + d];
            float b1 = Ks[(tx*4+1)*LDA + d];
            float b2 = Ks[(tx*4+2)*LDA + d];
            float b3 = Ks[(tx*4+3)*LDA + d];
            sacc[0][0]+=a0*b0; sacc[0][1]+=a0*b1; sacc[0][2]+=a0*b2; sacc[0][3]+=a0*b3;
            sacc[1][0]+=a1*b0; sacc[1][1]+=a1*b1; sacc[1][2]+=a1*b2; sacc[1][3]+=a1*b3;
            sacc[2][0]+=a2*b0; sacc[2][1]+=a2*b1; sacc[2][2]+=a2*b2; sacc[2][3]+=a2*b3;
            sacc[3][0]+=a3*b0; sacc[3][1]+=a3*b1; sacc[3][2]+=a3*b2; sacc[3][3]+=a3*b3;
        }

        const bool diag  = (kt == qt);
        const int  rowg0 = qt * 64 + ty * 4;
        const int  colg0 = kt * 64 + tx * 4;

        #pragma unroll
        for (int i = 0; i < 4; i++) {
            float sc[4];
            #pragma unroll
            for (int j = 0; j < 4; j++) {
                float val = sacc[i][j] * scale;
                if (diag && (colg0 + j > rowg0 + i)) val = -INFINITY;
                sc[j] = val;
            }
            float mx = fmaxf(fmaxf(sc[0], sc[1]), fmaxf(sc[2], sc[3]));
            #pragma unroll
            for (int off = 8; off; off >>= 1)
                mx = fmaxf(mx, __shfl_xor_sync(0xffffffffu, mx, off));
            const float mnew  = fmaxf(mrow[i], mx);
            const float alpha = __expf(mrow[i] - mnew);
            float psum = 0.f;
            #pragma unroll
            for (int j = 0; j < 4; j++) { sc[j] = __expf(sc[j] - mnew); psum += sc[j]; }
            #pragma unroll
            for (int off = 8; off; off >>= 1)
                psum += __shfl_xor_sync(0xffffffffu, psum, off);
            lrow[i] = lrow[i] * alpha + psum;
            mrow[i] = mnew;
            #pragma unroll
            for (int j = 0; j < 4; j++) {
                acc[i][j] *= alpha;
                Ps[(ty*4+i)*LDA + tx*4 + j] = sc[j];
            }
        }
        __syncthreads();

        // O += P V
        #pragma unroll 8
        for (int kk = 0; kk < 64; kk++) {
            float p0 = Ps[(ty*4+0)*LDA + kk];
            float p1 = Ps[(ty*4+1)*LDA + kk];
            float p2 = Ps[(ty*4+2)*LDA + kk];
            float p3 = Ps[(ty*4+3)*LDA + kk];
            float v0 = Vs[kk*LDA + tx*4 + 0];
            float v1 = Vs[kk*LDA + tx*4 + 1];
            float v2 = Vs[kk*LDA + tx*4 + 2];
            float v3 = Vs[kk*LDA + tx*4 + 3];
            acc[0][0]+=p0*v0; acc[0][1]+=p0*v1; acc[0][2]+=p0*v2; acc[0][3]+=p0*v3;
            acc[1][0]+=p1*v0; acc[1][1]+=p1*v1; acc[1][2]+=p1*v2; acc[1][3]+=p1*v3;
            acc[2][0]+=p2*v0; acc[2][1]+=p2*v1; acc[2][2]+=p2*v2; acc[2][3]+=p2*v3;
            acc[3][0]+=p3*v0; acc[3][1]+=p3*v1; acc[3][2]+=p3*v2; acc[3][3]+=p3*v3;
        }
        __syncthreads();
    }

    // Depth-memory slots: 8 extra keys/values per row, folded into the online softmax
    #pragma unroll
    for (int i = 0; i < 4; i++) {
        const int r  = ty * 4 + i;
        const int sg = qt * 64 + r;
        const float* pkb = pk + ((size_t)bh * S_ + sg) * (L_ * DH_);
        const float* pvb = pv + ((size_t)bh * S_ + sg) * (L_ * DH_);

        float qv0 = Qs[r*LDA + tx*4 + 0];
        float qv1 = Qs[r*LDA + tx*4 + 1];
        float qv2 = Qs[r*LDA + tx*4 + 2];
        float qv3 = Qs[r*LDA + tx*4 + 3];

        float sc[L_];
        #pragma unroll
        for (int l = 0; l < L_; l++) {
            float4 kv = *(const float4*)(pkb + l * DH_ + tx * 4);
            float part = qv0*kv.x + qv1*kv.y + qv2*kv.z + qv3*kv.w;
            #pragma unroll
            for (int off = 8; off; off >>= 1)
                part += __shfl_xor_sync(0xffffffffu, part, off);
            sc[l] = part * scale;
        }
        float mx = sc[0];
        #pragma unroll
        for (int l = 1; l < L_; l++) mx = fmaxf(mx, sc[l]);
        const float mnew  = fmaxf(mrow[i], mx);
        const float alpha = __expf(mrow[i] - mnew);
        float psum = 0.f;
        #pragma unroll
        for (int l = 0; l < L_; l++) { sc[l] = __expf(sc[l] - mnew); psum += sc[l]; }
        const float lnew = lrow[i] * alpha + psum;

        #pragma unroll
        for (int j = 0; j < 4; j++) acc[i][j] *= alpha;
        #pragma unroll
        for (int l = 0; l < L_; l++) {
            float4 vv = *(const float4*)(pvb + l * DH_ + tx * 4);
            acc[i][0] += sc[l] * vv.x;
            acc[i][1] += sc[l] * vv.y;
            acc[i][2] += sc[l] * vv.z;
            acc[i][3] += sc[l] * vv.w;
        }

        const float inv = 1.0f / lnew;
        float4 o;
        o.x = acc[i][0] * inv; o.y = acc[i][1] * inv;
        o.z = acc[i][2] * inv; o.w = acc[i][3] * inv;
        *(float4*)(ctx + ((size_t)(b * S_ + sg)) * D_ + h * DH_ + tx * 4) = o;
    }
}

// ---------------------------------------------------------------------------
extern "C" void kernel_launch(void* const* d_in, const int* in_sizes, int n_in,
                              void* d_out, int out_size)
{
    const float* x    = (const float*)d_in[0];
    const float* pk   = (const float*)d_in[1];
    const float* pv   = (const float*)d_in[2];
    const float* Wqkv = (const float*)d_in[3];
    const float* bqkv = (const float*)d_in[4];
    const float* Wk   = (const float*)d_in[5];
    const float* bk   = (const float*)d_in[6];
    const float* Wv   = (const float*)d_in[7];
    const float* bv   = (const float*)d_in[8];
    const float* Wo   = (const float*)d_in[9];
    const float* bo   = (const float*)d_in[10];

    float* out  = (float*)d_out;                         // [B,S,D]
    float* kcol = out  + (size_t)B_ * S_ * D_;           // [B,H,S,DH]
    float* vcol = kcol + (size_t)B_ * H_ * S_ * DH_;     // [B,H,S,DH]

    float *gq, *gk, *gv, *gctx;
    cudaGetSymbolAddress((void**)&gq,   g_q);
    cudaGetSymbolAddress((void**)&gk,   g_k);
    cudaGetSymbolAddress((void**)&gv,   g_v);
    cudaGetSymbolAddress((void**)&gctx, g_ctx);

    const size_t attn_smem = 4 * 64 * 65 * sizeof(float);   // 66,560 B
    cudaFuncSetAttribute(attn_kernel,
                         cudaFuncAttributeMaxDynamicSharedMemorySize,
                         (int)attn_smem);

    dim3 blk(256);

    // qkv fused projection -> g_q/g_k/g_v in [B,H,S,DH]
    gemm_bias_kernel<<<dim3(3*D_/128, M_/128), blk>>>(
        x, Wqkv, bqkv, gq, gk, gv, M_, 3*D_, D_, 2);

    // k_col / v_col -> straight into d_out (head-split layout)
    gemm_bias_kernel<<<dim3(D_/128, M_/128), blk>>>(
        x, Wk, bk, kcol, nullptr, nullptr, M_, D_, D_, 0);
    gemm_bias_kernel<<<dim3(D_/128, M_/128), blk>>>(
        x, Wv, bv, vcol, nullptr, nullptr, M_, D_, D_, 0);

    // attention -> g_ctx in [B,S,D]
    attn_kernel<<<dim3(S_/64, B_*H_), blk, attn_smem>>>(gq, gk, gv, pk, pv, gctx);

    // output projection -> d_out[0 : B*S*D]
    gemm_bias_kernel<<<dim3(D_/128, M_/128), blk>>>(
        gctx, Wo, bo, out, nullptr, nullptr, M_, D_, D_, 1);
}

// round 15
// speedup vs baseline: 1.0071x; 1.0071x over previous
#include <cuda_runtime.h>
#include <math.h>

// Problem constants
#define B_  2
#define S_  2048
#define D_  1024
#define H_  16
#define L_  8
#define DH_ 64
#define M_  (B_*S_)          // 4096 rows for all projections

// Scratch (device globals; no allocations allowed)
__device__ float g_q[(size_t)B_*H_*S_*DH_];
__device__ float g_k[(size_t)B_*H_*S_*DH_];
__device__ float g_v[(size_t)B_*H_*S_*DH_];
__device__ float g_ctx[(size_t)B_*S_*D_];

// ---------------------------------------------------------------------------
// Generic tiled GEMM:  C[r,c] = sum_k A[r,k] * W[c,k] + bias[c]
//   A: [M,K] row-major, W: [N,K] row-major.
//   mode 0: write head-split   -> C0[((b*H+h)*S+s)*DH+dh],  c = h*DH+dh (N=1024)
//   mode 1: write flat         -> C0[r*N + c]
//   mode 2: N=3072 qkv split   -> part = c/1024 selects C0/C1/C2, head-split
// Tile: 128x128x8, 256 threads, 8x8 microtile per thread.
// ---------------------------------------------------------------------------
__global__ void __launch_bounds__(256)
gemm_bias_kernel(const float* __restrict__ A, const float* __restrict__ W,
                 const float* __restrict__ bias,
                 float* __restrict__ C0, float* __restrict__ C1, float* __restrict__ C2,
                 int M, int N, int K, int mode)
{
    __shared__ __align__(16) float As[8][128];
    __shared__ __align__(16) float Ws[8][128];

    const int tid  = threadIdx.x;
    const int bx   = blockIdx.x;        // N tile
    const int by   = blockIdx.y;        // M tile
    const int row0 = by * 128;
    const int col0 = bx * 128;

    const int lr = tid >> 1;            // 0..127 : tile row
    const int lk = (tid & 1) * 4;       // 0 or 4 : k sub-chunk

    const float* Aptr = A + (size_t)(row0 + lr) * K + lk;
    const float* Wptr = W + (size_t)(col0 + lr) * K + lk;

    const int tx = tid & 15;            // 0..15  : col group (8 cols)
    const int ty = tid >> 4;            // 0..15  : row group (8 rows)

    float acc[8][8];
    #pragma unroll
    for (int i = 0; i < 8; i++)
        #pragma unroll
        for (int j = 0; j < 8; j++) acc[i][j] = 0.f;

    float4 av = *(const float4*)(Aptr);
    float4 wv = *(const float4*)(Wptr);

    for (int kt = 0; kt < K; kt += 8) {
        As[lk+0][lr] = av.x; As[lk+1][lr] = av.y; As[lk+2][lr] = av.z; As[lk+3][lr] = av.w;
        Ws[lk+0][lr] = wv.x; Ws[lk+1][lr] = wv.y; Ws[lk+2][lr] = wv.z; Ws[lk+3][lr] = wv.w;
        __syncthreads();

        if (kt + 8 < K) {               // prefetch next k-slab
            av = *(const float4*)(Aptr + kt + 8);
            wv = *(const float4*)(Wptr + kt + 8);
        }

        #pragma unroll
        for (int kk = 0; kk < 8; kk++) {
            float a[8], b[8];
            *(float4*)&a[0] = *(const float4*)&As[kk][ty*8];
            *(float4*)&a[4] = *(const float4*)&As[kk][ty*8+4];
            *(float4*)&b[0] = *(const float4*)&Ws[kk][tx*8];
            *(float4*)&b[4] = *(const float4*)&Ws[kk][tx*8+4];
            #pragma unroll
            for (int i = 0; i < 8; i++)
                #pragma unroll
                for (int j = 0; j < 8; j++)
                    acc[i][j] += a[i] * b[j];
        }
        __syncthreads();
    }

    // Epilogue
    const int cbase = col0 + tx * 8;    // 8 contiguous output cols
    float bia[8];
    *(float4*)&bia[0] = *(const float4*)(bias + cbase);
    *(float4*)&bia[4] = *(const float4*)(bias + cbase + 4);

    #pragma unroll
    for (int i = 0; i < 8; i++) {
        const int r  = row0 + ty * 8 + i;
        float vals[8];
        #pragma unroll
        for (int j = 0; j < 8; j++) vals[j] = acc[i][j] + bia[j];

        if (mode == 1) {
            float* p = C0 + (size_t)r * N + cbase;
            *(float4*)p       = *(float4*)&vals[0];
            *(float4*)(p + 4) = *(float4*)&vals[4];
        } else {
            const int b_ = r >> 11;              // r / S_
            const int s_ = r & (S_ - 1);
            int d0 = cbase;
            float* Cp = C0;
            if (mode == 2) {
                const int part = cbase >> 10;    // 0:q 1:k 2:v (tile never straddles)
                d0 = cbase & 1023;
                Cp = (part == 0) ? C0 : ((part == 1) ? C1 : C2);
            }
            const int h   = d0 >> 6;
            const int dh0 = d0 & 63;             // 8-block stays inside one head
            float* p = Cp + (((size_t)(b_ * H_ + h) * S_ + s_) * DH_ + dh0);
            *(float4*)p       = *(float4*)&vals[0];
            *(float4*)(p + 4) = *(float4*)&vals[4];
        }
    }
}

// ---------------------------------------------------------------------------
// Flash attention with joint softmax over [causal tokens + L depth-memory slots].
// Grid: (S/64, B*H). 256 threads. Br=Bc=64, DH=64.
// Each thread owns a 4x4 microtile: rows ty*4+i, cols tx*4+j.
// Row-wise softmax stats reduced over the 16 tx-lanes via shfl (16-lane groups).
// ctx written directly in [B, S, H*DH] layout for the output projection.
// ---------------------------------------------------------------------------
__global__ void __launch_bounds__(256)
attn_kernel(const float* __restrict__ q, const float* __restrict__ k,
            const float* __restrict__ v, const float* __restrict__ pk,
            const float* __restrict__ pv, float* __restrict__ ctx)
{
    extern __shared__ float sm[];
    const int LDA = 65;                 // pad to dodge bank conflicts
    float* Qs = sm;
    float* Ks = Qs + 64 * LDA;
    float* Vs = Ks + 64 * LDA;
    float* Ps = Vs + 64 * LDA;

    const int qt  = blockIdx.x;
    const int bh  = blockIdx.y;
    const int b   = bh >> 4;
    const int h   = bh & 15;
    const int tid = threadIdx.x;
    const int tx  = tid & 15;
    const int ty  = tid >> 4;

    const float* qb = q + ((size_t)bh * S_ + qt * 64) * DH_;
    const float* kb = k + (size_t)bh * S_ * DH_;
    const float* vb = v + (size_t)bh * S_ * DH_;

    // Load Q tile (64x64): each thread 4 float4
    {
        const int r  = tid >> 2;
        const int c0 = (tid & 3) * 16;
        #pragma unroll
        for (int u = 0; u < 4; u++) {
            float4 t = *(const float4*)(qb + r * DH_ + c0 + u * 4);
            Qs[r*LDA + c0 + u*4 + 0] = t.x;
            Qs[r*LDA + c0 + u*4 + 1] = t.y;
            Qs[r*LDA + c0 + u*4 + 2] = t.z;
            Qs[r*LDA + c0 + u*4 + 3] = t.w;
        }
    }

    float acc[4][4];
    float mrow[4], lrow[4];
    #pragma unroll
    for (int i = 0; i < 4; i++) {
        mrow[i] = -INFINITY; lrow[i] = 0.f;
        #pragma unroll
        for (int j = 0; j < 4; j++) acc[i][j] = 0.f;
    }
    __syncthreads();

    const float scale = 0.125f;         // 1/sqrt(64)

    for (int kt = 0; kt <= qt; kt++) {
        // Load K/V tiles
        {
            const int r  = tid >> 2;
            const int c0 = (tid & 3) * 16;
            const float* kp = kb + ((size_t)kt * 64 + r) * DH_ + c0;
            const float* vp = vb + ((size_t)kt * 64 + r) * DH_ + c0;
            #pragma unroll
            for (int u = 0; u < 4; u++) {
                float4 t = *(const float4*)(kp + u * 4);
                Ks[r*LDA + c0 + u*4 + 0] = t.x;
                Ks[r*LDA + c0 + u*4 + 1] = t.y;
                Ks[r*LDA + c0 + u*4 + 2] = t.z;
                Ks[r*LDA + c0 + u*4 + 3] = t.w;
                float4 t2 = *(const float4*)(vp + u * 4);
                Vs[r*LDA + c0 + u*4 + 0] = t2.x;
                Vs[r*LDA + c0 + u*4 + 1] = t2.y;
                Vs[r*LDA + c0 + u*4 + 2] = t2.z;
                Vs[r*LDA + c0 + u*4 + 3] = t2.w;
            }
        }
        __syncthreads();

        // S = Q K^T (4x4 per thread)
        float sacc[4][4];
        #pragma unroll
        for (int i = 0; i < 4; i++)
            #pragma unroll
            for (int j = 0; j < 4; j++) sacc[i][j] = 0.f;

        #pragma unroll 8
        for (int d = 0; d < 64; d++) {
            float a0 = Qs[(ty*4+0)*LDA + d];
            float a1 = Qs[(ty*4+1)*LDA + d];
            float a2 = Qs[(ty*4+2)*LDA + d];
            float a3 = Qs[(ty*4+3)*LDA + d];
            float b0 = Ks[(tx*4+0)*LDA + d];
            float b1 = Ks[(tx*4+1)*LDA + d];
            float b2 = Ks[(tx*4+2)*LDA + d];
            float b3 = Ks[(tx*4+3)*LDA + d];
            sacc[0][0]+=a0*b0; sacc[0][1]+=a0*b1; sacc[0][2]+=a0*b2; sacc[0][3]+=a0*b3;
            sacc[1][0]+=a1*b0; sacc[1][1]+=a1*b1; sacc[1][2]+=a1*b2; sacc[1][3]+=a1*b3;
            sacc[2][0]+=a2*b0; sacc[2][1]+=a2*b1; sacc[2][2]+=a2*b2; sacc[2][3]+=a2*b3;
            sacc[3][0]+=a3*b0; sacc[3][1]+=a3*b1; sacc[3][2]+=a3*b2; sacc[3][3]+=a3*b3;
        }

        const bool diag  = (kt == qt);
        const int  rowg0 = qt * 64 + ty * 4;
        const int  colg0 = kt * 64 + tx * 4;

        #pragma unroll
        for (int i = 0; i < 4; i++) {
            float sc[4];
            #pragma unroll
            for (int j = 0; j < 4; j++) {
                float val = sacc[i][j] * scale;
                if (diag && (colg0 + j > rowg0 + i)) val = -INFINITY;
                sc[j] = val;
            }
            float mx = fmaxf(fmaxf(sc[0], sc[1]), fmaxf(sc[2], sc[3]));
            #pragma unroll
            for (int off = 8; off; off >>= 1)
                mx = fmaxf(mx, __shfl_xor_sync(0xffffffffu, mx, off));
            const float mnew  = fmaxf(mrow[i], mx);
            const float alpha = __expf(mrow[i] - mnew);
            float psum = 0.f;
            #pragma unroll
            for (int j = 0; j < 4; j++) { sc[j] = __expf(sc[j] - mnew); psum += sc[j]; }
            #pragma unroll
            for (int off = 8; off; off >>= 1)
                psum += __shfl_xor_sync(0xffffffffu, psum, off);
            lrow[i] = lrow[i] * alpha + psum;
            mrow[i] = mnew;
            #pragma unroll
            for (int j = 0; j < 4; j++) {
                acc[i][j] *= alpha;
                Ps[(ty*4+i)*LDA + tx*4 + j] = sc[j];
            }
        }
        __syncthreads();

        // O += P V
        #pragma unroll 8
        for (int kk = 0; kk < 64; kk++) {
            float p0 = Ps[(ty*4+0)*LDA + kk];
            float p1 = Ps[(ty*4+1)*LDA + kk];
            float p2 = Ps[(ty*4+2)*LDA + kk];
            float p3 = Ps[(ty*4+3)*LDA + kk];
            float v0 = Vs[kk*LDA + tx*4 + 0];
            float v1 = Vs[kk*LDA + tx*4 + 1];
            float v2 = Vs[kk*LDA + tx*4 + 2];
            float v3 = Vs[kk*LDA + tx*4 + 3];
            acc[0][0]+=p0*v0; acc[0][1]+=p0*v1; acc[0][2]+=p0*v2; acc[0][3]+=p0*v3;
            acc[1][0]+=p1*v0; acc[1][1]+=p1*v1; acc[1][2]+=p1*v2; acc[1][3]+=p1*v3;
            acc[2][0]+=p2*v0; acc[2][1]+=p2*v1; acc[2][2]+=p2*v2; acc[2][3]+=p2*v3;
            acc[3][0]+=p3*v0; acc[3][1]+=p3*v1; acc[3][2]+=p3*v2; acc[3][3]+=p3*v3;
        }
        __syncthreads();
    }

    // Depth-memory slots: 8 extra keys/values per row, folded into the online softmax
    #pragma unroll
    for (int i = 0; i < 4; i++) {
        const int r  = ty * 4 + i;
        const int sg = qt * 64 + r;
        const float* pkb = pk + ((size_t)bh * S_ + sg) * (L_ * DH_);
        const float* pvb = pv + ((size_t)bh * S_ + sg) * (L_ * DH_);

        float qv0 = Qs[r*LDA + tx*4 + 0];
        float qv1 = Qs[r*LDA + tx*4 + 1];
        float qv2 = Qs[r*LDA + tx*4 + 2];
        float qv3 = Qs[r*LDA + tx*4 + 3];

        float sc[L_];
        #pragma unroll
        for (int l = 0; l < L_; l++) {
            float4 kv = *(const float4*)(pkb + l * DH_ + tx * 4);
            float part = qv0*kv.x + qv1*kv.y + qv2*kv.z + qv3*kv.w;
            #pragma unroll
            for (int off = 8; off; off >>= 1)
                part += __shfl_xor_sync(0xffffffffu, part, off);
            sc[l] = part * scale;
        }
        float mx = sc[0];
        #pragma unroll
        for (int l = 1; l < L_; l++) mx = fmaxf(mx, sc[l]);
        const float mnew  = fmaxf(mrow[i], mx);
        const float alpha = __expf(mrow[i] - mnew);
        float psum = 0.f;
        #pragma unroll
        for (int l = 0; l < L_; l++) { sc[l] = __expf(sc[l] - mnew); psum += sc[l]; }
        const float lnew = lrow[i] * alpha + psum;

        #pragma unroll
        for (int j = 0; j < 4; j++) acc[i][j] *= alpha;
        #pragma unroll
        for (int l = 0; l < L_; l++) {
            float4 vv = *(const float4*)(pvb + l * DH_ + tx * 4);
            acc[i][0] += sc[l] * vv.x;
            acc[i][1] += sc[l] * vv.y;
            acc[i][2] += sc[l] * vv.z;
            acc[i][3] += sc[l] * vv.w;
        }

        const float inv = 1.0f / lnew;
        float4 o;
        o.x = acc[i][0] * inv; o.y = acc[i][1] * inv;
        o.z = acc[i][2] * inv; o.w = acc[i][3] * inv;
        *(float4*)(ctx + ((size_t)(b * S_ + sg)) * D_ + h * DH_ + tx * 4) = o;
    }
}

// ---------------------------------------------------------------------------
extern "C" void kernel_launch(void* const* d_in, const int* in_sizes, int n_in,
                              void* d_out, int out_size)
{
    const float* x    = (const float*)d_in[0];
    const float* pk   = (const float*)d_in[1];
    const float* pv   = (const float*)d_in[2];
    const float* Wqkv = (const float*)d_in[3];
    const float* bqkv = (const float*)d_in[4];
    const float* Wk   = (const float*)d_in[5];
    const float* bk   = (const float*)d_in[6];
    const float* Wv   = (const float*)d_in[7];
    const float* bv   = (const float*)d_in[8];
    const float* Wo   = (const float*)d_in[9];
    const float* bo   = (const float*)d_in[10];

    float* out  = (float*)d_out;                         // [B,S,D]
    float* kcol = out  + (size_t)B_ * S_ * D_;           // [B,H,S,DH]
    float* vcol = kcol + (size_t)B_ * H_ * S_ * DH_;     // [B,H,S,DH]

    float *gq, *gk, *gv, *gctx;
    cudaGetSymbolAddress((void**)&gq,   g_q);
    cudaGetSymbolAddress((void**)&gk,   g_k);
    cudaGetSymbolAddress((void**)&gv,   g_v);
    cudaGetSymbolAddress((void**)&gctx, g_ctx);

    const size_t attn_smem = 4 * 64 * 65 * sizeof(float);   // 66,560 B
    cudaFuncSetAttribute(attn_kernel,
                         cudaFuncAttributeMaxDynamicSharedMemorySize,
                         (int)attn_smem);

    dim3 blk(256);

    // qkv fused projection -> g_q/g_k/g_v in [B,H,S,DH]
    gemm_bias_kernel<<<dim3(3*D_/128, M_/128), blk>>>(
        x, Wqkv, bqkv, gq, gk, gv, M_, 3*D_, D_, 2);

    // k_col / v_col -> straight into d_out (head-split layout)
    gemm_bias_kernel<<<dim3(D_/128, M_/128), blk>>>(
        x, Wk, bk, kcol, nullptr, nullptr, M_, D_, D_, 0);
    gemm_bias_kernel<<<dim3(D_/128, M_/128), blk>>>(
        x, Wv, bv, vcol, nullptr, nullptr, M_, D_, D_, 0);

    // attention -> g_ctx in [B,S,D]
    attn_kernel<<<dim3(S_/64, B_*H_), blk, attn_smem>>>(gq, gk, gv, pk, pv, gctx);

    // output projection -> d_out[0 : B*S*D]
    gemm_bias_kernel<<<dim3(D_/128, M_/128), blk>>>(
        gctx, Wo, bo, out, nullptr, nullptr, M_, D_, D_, 1);
}